// round 16
// baseline (speedup 1.0000x reference)
#include <cuda_runtime.h>
#include <cuda_fp16.h>
#include <cstdint>
#include <math.h>

#define B_TOTAL 65536
#define KDIM 512
#define T_ROWS 49152               // rows via tensor path (384 m_blks)
#define F_ROWS 16384               // rows via FFMA path (128 blocks)

#define A_BLK_U4 8192              // uint4 per m_blk per limb
#define W_NBLK_U4 8192
#define NSTAGE 3
#define STAGE_WORDS 8192                         // 32 KB per stage
#define SMEM_BYTES (NSTAGE * STAGE_WORDS * 4)    // 96 KB dynamic

// Scratch: limb ping-pong (tensor rows), fp32 ping-pong (FFMA rows), packed weights
__device__ uint4 g_A0a[384 * A_BLK_U4];
__device__ uint4 g_A1a[384 * A_BLK_U4];
__device__ uint4 g_A0b[384 * A_BLK_U4];
__device__ uint4 g_A1b[384 * A_BLK_U4];
__device__ uint4 g_W0[21 * W_NBLK_U4];
__device__ uint4 g_W1[21 * W_NBLK_U4];
__device__ float g_Fa[(size_t)F_ROWS * KDIM];
__device__ float g_Fb[(size_t)F_ROWS * KDIM];

__device__ __forceinline__ float act_clip(float h, int f, float mx) {
    float o;
    if (f == 0) {
        o = fmaxf(h, 0.0f);                       // ReLU
    } else if (f == 1) {
        o = 1.0f / (1.0f + __expf(-h));           // Sigmoid
    } else if (f == 2) {
        o = tanhf(h);                             // Tanh
    } else if (f == 3) {
        o = (h > 0.0f) ? h : 0.1f * h;            // LeakyReLU(0.1)
    } else {
        const float sc = 1.0507009873554805f;     // SELU
        const float al = 1.6732632423543772f;
        o = (h > 0.0f) ? sc * h : sc * al * (__expf(h) - 1.0f);
    }
    return fminf(o, mx);
}

__device__ __forceinline__ void split2(float x, float y, uint32_t& w0, uint32_t& w1) {
    const __half hx = __float2half_rn(x);
    const __half hy = __float2half_rn(y);
    const __half lx = __float2half_rn(x - __half2float(hx));
    const __half ly = __float2half_rn(y - __half2float(hy));
    w0 = (uint32_t)__half_as_ushort(hx) | ((uint32_t)__half_as_ushort(hy) << 16);
    w1 = (uint32_t)__half_as_ushort(lx) | ((uint32_t)__half_as_ushort(ly) << 16);
}

__device__ __forceinline__ void mma16(float* d, const uint4& a, uint32_t b0, uint32_t b1) {
    asm("mma.sync.aligned.m16n8k16.row.col.f32.f16.f16.f32 "
        "{%0,%1,%2,%3}, {%4,%5,%6,%7}, {%8,%9}, {%0,%1,%2,%3};"
        : "+f"(d[0]), "+f"(d[1]), "+f"(d[2]), "+f"(d[3])
        : "r"(a.x), "r"(a.y), "r"(a.z), "r"(a.w), "r"(b0), "r"(b1));
}

__device__ __forceinline__ void cp_async16(uint32_t dst, const void* src) {
    asm volatile("cp.async.cg.shared.global [%0], [%1], 16;" :: "r"(dst), "l"(src));
}

// ---- pack: fp32 row-major -> fp16 limb fragment layout (tensor rows only) ----
__global__ void __launch_bounds__(256)
pack_a16(const float* __restrict__ src, uint4* __restrict__ d0, uint4* __restrict__ d1)
{
    const uint32_t gid = blockIdx.x * 256 + threadIdx.x;   // 384*8192 = 3,145,728
    const int lane = gid & 31;
    const int mt   = (gid >> 5) & 7;
    const int k16  = (gid >> 8) & 1;
    const int kc   = (gid >> 9) & 15;
    const int mblk = gid >> 13;
    const int g = lane >> 2, tig = lane & 3;
    const int row0 = mblk * 128 + mt * 16 + g;
    const int k0 = kc * 32 + k16 * 16 + tig * 2;
    const float2 p00 = *(const float2*)(src + (size_t)row0 * KDIM + k0);
    const float2 p10 = *(const float2*)(src + (size_t)(row0 + 8) * KDIM + k0);
    const float2 p01 = *(const float2*)(src + (size_t)row0 * KDIM + k0 + 8);
    const float2 p11 = *(const float2*)(src + (size_t)(row0 + 8) * KDIM + k0 + 8);
    uint4 h, l;
    split2(p00.x, p00.y, h.x, l.x);
    split2(p10.x, p10.y, h.y, l.y);
    split2(p01.x, p01.y, h.z, l.z);
    split2(p11.x, p11.y, h.w, l.w);
    d0[gid] = h;
    d1[gid] = l;
}

__global__ void __launch_bounds__(256)
pack_w16(const float* __restrict__ src, uint4* __restrict__ d0, uint4* __restrict__ d1)
{
    const uint32_t gid = blockIdx.x * 256 + threadIdx.x;
    const int lane = gid & 31;
    const int np   = (gid >> 5) & 7;
    const int k16  = (gid >> 8) & 1;
    const int kc   = (gid >> 9) & 15;
    const int nblk = gid >> 13;
    const int g = lane >> 2, tig = lane & 3;
    const int n0 = nblk * 128 + np * 16 + g;
    const int k0 = kc * 32 + k16 * 16 + tig * 2;
    const float2 q00 = *(const float2*)(src + (size_t)n0 * KDIM + k0);
    const float2 q01 = *(const float2*)(src + (size_t)n0 * KDIM + k0 + 8);
    const float2 q10 = *(const float2*)(src + (size_t)(n0 + 8) * KDIM + k0);
    const float2 q11 = *(const float2*)(src + (size_t)(n0 + 8) * KDIM + k0 + 8);
    uint4 h, l;
    split2(q00.x, q00.y, h.x, l.x);
    split2(q01.x, q01.y, h.y, l.y);
    split2(q10.x, q10.y, h.z, l.z);
    split2(q11.x, q11.y, h.w, l.w);
    d0[gid] = h;
    d1[gid] = l;
}

// ---- heterogeneous layer kernel ----
// bid pattern: r = bid&15; FFMA iff (r+(r>>2))&3 == 3 (r in {3,6,9,12}) -> exactly 1/4.
// Tensor CTAs: limb-format GEMM on rows 0..T_ROWS-1 (unchanged core).
// FFMA CTAs: fp32 SGEMM (R4 core) on rows T_ROWS.. (local row space of Af/Cf).
__global__ void __launch_bounds__(256, 2)
fused_hybrid(const uint4* __restrict__ A0, const uint4* __restrict__ A1,
             const uint4* __restrict__ B0, const uint4* __restrict__ B1,
             uint32_t* __restrict__ C0, uint32_t* __restrict__ C1,
             const float* __restrict__ Af, const float* __restrict__ Wf,
             float* __restrict__ Cf,
             const float* __restrict__ bias,
             const int*   __restrict__ fid,
             const float* __restrict__ mx,
             float* __restrict__ Cout_t,
             int Nout, int n_tiles, int split_out)
{
    extern __shared__ __align__(16) uint32_t smw[];
    __shared__ __align__(16) float sAf[2][8][128];
    __shared__ __align__(16) float sBf[2][8][128];

    const int tid = threadIdx.x;
    const int bid = blockIdx.x;
    const int q = bid >> 4;
    const int r = bid & 15;
    const bool is_f = (((r + (r >> 2)) & 3) == 3);

    if (is_f) {
        // ================= FFMA path (fp32, exact R4 core) =================
        const int fidx = q * 4 + (r - 3) / 3;       // r in {3,6,9,12} -> 0..3
        const int fm = fidx / n_tiles;
        const int fn = fidx - fm * n_tiles;
        const int bm = fm * 128;                     // local row base
        const int bn = fn * 128;
        const int tx = tid & 15;
        const int ty = tid >> 4;
        const int lrow = tid >> 1;
        const int lk = (tid & 1) * 4;

        const float* Ap = Af + (size_t)(bm + lrow) * KDIM + lk;
        const float* Wp = Wf + (size_t)(bn + lrow) * KDIM + lk;

        float acc[8][8];
        #pragma unroll
        for (int i = 0; i < 8; ++i)
            #pragma unroll
            for (int j = 0; j < 8; ++j) acc[i][j] = 0.0f;

        // prologue: stage k-tile 0
        float4 a4 = *(const float4*)Ap;
        float4 b4 = *(const float4*)Wp;
        sAf[0][lk + 0][lrow] = a4.x; sAf[0][lk + 1][lrow] = a4.y;
        sAf[0][lk + 2][lrow] = a4.z; sAf[0][lk + 3][lrow] = a4.w;
        sBf[0][lk + 0][lrow] = b4.x; sBf[0][lk + 1][lrow] = b4.y;
        sBf[0][lk + 2][lrow] = b4.z; sBf[0][lk + 3][lrow] = b4.w;
        __syncthreads();

        int buf = 0;
        constexpr int NT = KDIM / 8;   // 64 k-tiles
        for (int kt = 0; kt < NT; ++kt) {
            if (kt + 1 < NT) {
                a4 = *(const float4*)(Ap + (kt + 1) * 8);
                b4 = *(const float4*)(Wp + (kt + 1) * 8);
            }
            #pragma unroll
            for (int k = 0; k < 8; ++k) {
                float4 ar0 = *(const float4*)&sAf[buf][k][ty * 8];
                float4 ar1 = *(const float4*)&sAf[buf][k][ty * 8 + 4];
                float4 br0 = *(const float4*)&sBf[buf][k][tx * 8];
                float4 br1 = *(const float4*)&sBf[buf][k][tx * 8 + 4];
                float ar[8] = {ar0.x, ar0.y, ar0.z, ar0.w, ar1.x, ar1.y, ar1.z, ar1.w};
                float br[8] = {br0.x, br0.y, br0.z, br0.w, br1.x, br1.y, br1.z, br1.w};
                #pragma unroll
                for (int i = 0; i < 8; ++i)
                    #pragma unroll
                    for (int j = 0; j < 8; ++j)
                        acc[i][j] = fmaf(ar[i], br[j], acc[i][j]);
            }
            if (kt + 1 < NT) {
                const int nb = buf ^ 1;
                sAf[nb][lk + 0][lrow] = a4.x; sAf[nb][lk + 1][lrow] = a4.y;
                sAf[nb][lk + 2][lrow] = a4.z; sAf[nb][lk + 3][lrow] = a4.w;
                sBf[nb][lk + 0][lrow] = b4.x; sBf[nb][lk + 1][lrow] = b4.y;
                sBf[nb][lk + 2][lrow] = b4.z; sBf[nb][lk + 3][lrow] = b4.w;
                __syncthreads();
                buf = nb;
            }
        }

        const int col0 = bn + tx * 8;
        float bv[8], mv[8];
        int   fv[8];
        #pragma unroll
        for (int j = 0; j < 8; ++j) {
            bv[j] = __ldg(bias + col0 + j);
            fv[j] = __ldg(fid  + col0 + j);
            mv[j] = __ldg(mx   + col0 + j);
        }
        #pragma unroll
        for (int i = 0; i < 8; ++i) {
            const int row = bm + ty * 8 + i;       // local row
            float v[8];
            #pragma unroll
            for (int j = 0; j < 8; ++j)
                v[j] = act_clip(acc[i][j] + bv[j], fv[j], mv[j]);
            *(float4*)(Cf + (size_t)row * Nout + col0)     = make_float4(v[0], v[1], v[2], v[3]);
            *(float4*)(Cf + (size_t)row * Nout + col0 + 4) = make_float4(v[4], v[5], v[6], v[7]);
        }
        return;
    }

    // ================= Tensor path (fp16 2-limb, unchanged core) =================
    const int nf = (r > 2) + (r > 5) + (r > 8) + (r > 11);
    const int tidx = q * 12 + (r - nf);
    const int tm = tidx / n_tiles;
    const int tn = tidx - tm * n_tiles;

    const int w   = tid >> 5;
    const int l   = tid & 31;
    const int bn  = tn * 128;
    const int wm  = w & 3;
    const int wn  = w >> 2;

    const uint32_t smem_addr = (uint32_t)__cvta_generic_to_shared(smw);
    const size_t a_base = (size_t)tm * A_BLK_U4;
    const size_t b_base = (size_t)tn * W_NBLK_U4;

    float acc[2][8][4];
    #pragma unroll
    for (int i = 0; i < 2; ++i)
        #pragma unroll
        for (int u = 0; u < 8; ++u)
            #pragma unroll
            for (int rr = 0; rr < 4; ++rr) acc[i][u][rr] = 0.0f;

    #define ISSUE_CHUNK(kc_) do {                                             \
        const uint32_t dstb = smem_addr + ((kc_) % NSTAGE) * (STAGE_WORDS*4); \
        const uint4* pA0 = A0 + a_base + (size_t)(kc_) * 512;                 \
        const uint4* pA1 = A1 + a_base + (size_t)(kc_) * 512;                 \
        const uint4* pB0 = B0 + b_base + (size_t)(kc_) * 512;                 \
        const uint4* pB1 = B1 + b_base + (size_t)(kc_) * 512;                 \
        _Pragma("unroll")                                                     \
        for (int j = 0; j < 2; ++j) {                                         \
            const int g16 = tid + j * 256;                                    \
            cp_async16(dstb +         g16 * 16, pA0 + g16);                   \
            cp_async16(dstb +  8192 + g16 * 16, pA1 + g16);                   \
            cp_async16(dstb + 16384 + g16 * 16, pB0 + g16);                   \
            cp_async16(dstb + 24576 + g16 * 16, pB1 + g16);                   \
        }                                                                     \
        asm volatile("cp.async.commit_group;" ::: "memory");                  \
    } while (0)

    ISSUE_CHUNK(0);
    ISSUE_CHUNK(1);

    constexpr int NCHUNK = KDIM / 32;   // 16
    for (int kc = 0; kc < NCHUNK; ++kc) {
        asm volatile("cp.async.wait_group 1;" ::: "memory");
        __syncthreads();
        if (kc + 2 < NCHUNK) ISSUE_CHUNK(kc + 2);

        const uint32_t* sw = smw + (kc % NSTAGE) * STAGE_WORDS;
        #pragma unroll
        for (int k16 = 0; k16 < 2; ++k16) {
            const uint32_t* awb = sw + k16 * 1024;
            const uint4 ah0 = *(const uint4*)(awb + (wm * 2 + 0) * 128 + l * 4);
            const uint4 ah1 = *(const uint4*)(awb + (wm * 2 + 1) * 128 + l * 4);
            const uint4 al0 = *(const uint4*)(awb + 2048 + (wm * 2 + 0) * 128 + l * 4);
            const uint4 al1 = *(const uint4*)(awb + 2048 + (wm * 2 + 1) * 128 + l * 4);
            const uint32_t* bwb = sw + 4096 + k16 * 1024;
            uint4 bh[4], bl[4];
            #pragma unroll
            for (int pp = 0; pp < 4; ++pp) {
                const int np = wn * 4 + pp;
                bh[pp] = *(const uint4*)(bwb + np * 128 + l * 4);
                bl[pp] = *(const uint4*)(bwb + 2048 + np * 128 + l * 4);
            }
            #pragma unroll
            for (int pp = 0; pp < 4; ++pp) {
                mma16(acc[0][pp * 2],     ah0, bh[pp].x, bh[pp].y);
                mma16(acc[1][pp * 2],     ah1, bh[pp].x, bh[pp].y);
                mma16(acc[0][pp * 2 + 1], ah0, bh[pp].z, bh[pp].w);
                mma16(acc[1][pp * 2 + 1], ah1, bh[pp].z, bh[pp].w);
            }
            #pragma unroll
            for (int pp = 0; pp < 4; ++pp) {
                mma16(acc[0][pp * 2],     ah0, bl[pp].x, bl[pp].y);
                mma16(acc[1][pp * 2],     ah1, bl[pp].x, bl[pp].y);
                mma16(acc[0][pp * 2 + 1], ah0, bl[pp].z, bl[pp].w);
                mma16(acc[1][pp * 2 + 1], ah1, bl[pp].z, bl[pp].w);
            }
            #pragma unroll
            for (int pp = 0; pp < 4; ++pp) {
                mma16(acc[0][pp * 2],     al0, bh[pp].x, bh[pp].y);
                mma16(acc[1][pp * 2],     al1, bh[pp].x, bh[pp].y);
                mma16(acc[0][pp * 2 + 1], al0, bh[pp].z, bh[pp].w);
                mma16(acc[1][pp * 2 + 1], al1, bh[pp].z, bh[pp].w);
            }
        }
    }

    const int g = l >> 2;
    #pragma unroll
    for (int u = 0; u < 8; ++u) {
        const int col = bn + wn * 64 + u * 8 + (l & 3) * 2;
        const float bv0 = __ldg(bias + col);
        const float bv1 = __ldg(bias + col + 1);
        const int   f0  = __ldg(fid + col);
        const int   f1  = __ldg(fid + col + 1);
        const float m0  = __ldg(mx + col);
        const float m1  = __ldg(mx + col + 1);
        #pragma unroll
        for (int i = 0; i < 2; ++i) {
            const float* a4 = acc[i][u];
            const float v00 = act_clip(a4[0] + bv0, f0, m0);
            const float v01 = act_clip(a4[1] + bv1, f1, m1);
            const float v10 = act_clip(a4[2] + bv0, f0, m0);
            const float v11 = act_clip(a4[3] + bv1, f1, m1);
            if (split_out) {
                const int kc_  = col >> 5;
                const int k16_ = (col >> 4) & 1;
                const int kb   = (col >> 3) & 1;
                const int mt_  = wm * 2 + i;
                const size_t wb =
                    ((((size_t)tm * 16 + kc_) * 2 + k16_) * 8 + mt_) * 128
                    + (size_t)l * 4;
                uint32_t w0h, w0l, w1h, w1l;
                split2(v00, v01, w0h, w0l);
                split2(v10, v11, w1h, w1l);
                C0[wb + 2 * kb]     = w0h;  C1[wb + 2 * kb]     = w0l;
                C0[wb + 1 + 2 * kb] = w1h;  C1[wb + 1 + 2 * kb] = w1l;
            } else {
                const int row0 = tm * 128 + wm * 32 + i * 16 + g;
                *(float2*)(Cout_t + (size_t)row0 * Nout + col)       = make_float2(v00, v01);
                *(float2*)(Cout_t + (size_t)(row0 + 8) * Nout + col) = make_float2(v10, v11);
            }
        }
    }
}

extern "C" void kernel_launch(void* const* d_in, const int* in_sizes, int n_in,
                              void* d_out, int out_size) {
    const float* x      = (const float*)d_in[0];   // [65536, 512]
    const float* W_in   = (const float*)d_in[1];
    const float* b_in   = (const float*)d_in[2];
    const float* W_h    = (const float*)d_in[3];
    const float* b_h    = (const float*)d_in[4];
    const float* W_out  = (const float*)d_in[5];
    const float* b_out  = (const float*)d_in[6];
    const float* m_in   = (const float*)d_in[7];
    const float* m_h    = (const float*)d_in[8];
    const float* m_out  = (const float*)d_in[9];
    const int*   fid_in = (const int*)d_in[10];
    const int*   fid_h  = (const int*)d_in[11];
    const int*   fid_out= (const int*)d_in[12];
    float* out = (float*)d_out;                    // [65536, 128]

    uint4 *A0a, *A1a, *A0b, *A1b, *W0, *W1;
    float *Fa, *Fb;
    cudaGetSymbolAddress((void**)&A0a, g_A0a);
    cudaGetSymbolAddress((void**)&A1a, g_A1a);
    cudaGetSymbolAddress((void**)&A0b, g_A0b);
    cudaGetSymbolAddress((void**)&A1b, g_A1b);
    cudaGetSymbolAddress((void**)&W0, g_W0);
    cudaGetSymbolAddress((void**)&W1, g_W1);
    cudaGetSymbolAddress((void**)&Fa, g_Fa);
    cudaGetSymbolAddress((void**)&Fb, g_Fb);

    cudaFuncSetAttribute(fused_hybrid,
                         cudaFuncAttributeMaxDynamicSharedMemorySize, SMEM_BYTES);

    // one-time packing: tensor rows of x + all weights
    pack_a16<<<12288, 256>>>(x, A0a, A1a);                                   // 384 m_blks
    pack_w16<<<128, 256>>>(W_in,  W0,                 W1);
    pack_w16<<<512, 256>>>(W_h,   W0 + 4 * W_NBLK_U4,  W1 + 4 * W_NBLK_U4);
    pack_w16<<<32, 256>>>(W_out,  W0 + 20 * W_NBLK_U4, W1 + 20 * W_NBLK_U4);

    const float* xF = x + (size_t)T_ROWS * KDIM;   // FFMA rows of input

    // input layer
    fused_hybrid<<<2048, 256, SMEM_BYTES>>>(A0a, A1a, W0, W1,
                                            (uint32_t*)A0b, (uint32_t*)A1b,
                                            xF, W_in, Fb,
                                            b_in, fid_in, m_in,
                                            nullptr, 512, 4, 1);

    // 4 hidden layers, ping-pong
    const uint4* c0 = A0b; const uint4* c1 = A1b;
    uint4* n0 = A0a;       uint4* n1 = A1a;
    const float* fc = Fb;  float* fn = Fa;
    for (int i = 0; i < 4; ++i) {
        const size_t woff = (size_t)(4 + 4 * i) * W_NBLK_U4;
        fused_hybrid<<<2048, 256, SMEM_BYTES>>>(c0, c1, W0 + woff, W1 + woff,
                                                (uint32_t*)n0, (uint32_t*)n1,
                                                fc, W_h + (size_t)i * 512 * 512, fn,
                                                b_h + i * 512, fid_h + i * 512, m_h + i * 512,
                                                nullptr, 512, 4, 1);
        uint4* t0 = n0; uint4* t1 = n1;
        n0 = (uint4*)c0; n1 = (uint4*)c1;
        c0 = t0; c1 = t1;
        float* tf = fn; fn = (float*)fc; fc = tf;
    }

    // output layer: tensor -> out rows 0..T_ROWS-1; FFMA -> out rows T_ROWS..
    fused_hybrid<<<512, 256, SMEM_BYTES>>>(c0, c1,
                                           W0 + 20 * W_NBLK_U4, W1 + 20 * W_NBLK_U4,
                                           nullptr, nullptr,
                                           fc, W_out, out + (size_t)T_ROWS * 128,
                                           b_out, fid_out, m_out,
                                           out, 128, 1, 0);
}

// round 17
// speedup vs baseline: 1.6498x; 1.6498x over previous
#include <cuda_runtime.h>
#include <cuda_fp16.h>
#include <cstdint>
#include <math.h>

#define B_TOTAL 65536
#define KDIM 512

// Packed fp16 limb layout.
// A (per m_blk of 128 rows): word idx = ((((m_blk*16+kc)*2+k16)*8+mt)*32+lane)*4 + r
// B (per n_blk of 128 cols): word idx = ((((n_blk*16+kc)*2+k16)*8+np)*32+lane)*4 + r
#define A_BLK_U4 8192              // uint4 per m_blk per limb
#define W_NBLK_U4 8192             // uint4 per n_blk per limb
#define NSTAGE 3
#define STAGE_WORDS 8192                         // 32 KB per stage
#define SMEM_BYTES (NSTAGE * STAGE_WORDS * 4)    // 96 KB

// Scratch (allocation-free): A limb ping-pong + packed weights (21 n_blks)
__device__ uint4 g_A0a[4194304];
__device__ uint4 g_A1a[4194304];
__device__ uint4 g_A0b[4194304];
__device__ uint4 g_A1b[4194304];
__device__ uint4 g_W0[21 * W_NBLK_U4];
__device__ uint4 g_W1[21 * W_NBLK_U4];

__device__ __forceinline__ float act_clip(float h, int f, float mx) {
    float o;
    if (f == 0) {
        o = fmaxf(h, 0.0f);                       // ReLU
    } else if (f == 1) {
        o = 1.0f / (1.0f + __expf(-h));           // Sigmoid
    } else if (f == 2) {
        o = tanhf(h);                             // Tanh
    } else if (f == 3) {
        o = (h > 0.0f) ? h : 0.1f * h;            // LeakyReLU(0.1)
    } else {
        const float sc = 1.0507009873554805f;     // SELU
        const float al = 1.6732632423543772f;
        o = (h > 0.0f) ? sc * h : sc * al * (__expf(h) - 1.0f);
    }
    return fminf(o, mx);
}

// fp16 two-limb split of a float pair -> (h0 word, h1 word), low half = first element
__device__ __forceinline__ void split2(float x, float y, uint32_t& w0, uint32_t& w1) {
    const __half hx = __float2half_rn(x);
    const __half hy = __float2half_rn(y);
    const __half lx = __float2half_rn(x - __half2float(hx));
    const __half ly = __float2half_rn(y - __half2float(hy));
    w0 = (uint32_t)__half_as_ushort(hx) | ((uint32_t)__half_as_ushort(hy) << 16);
    w1 = (uint32_t)__half_as_ushort(lx) | ((uint32_t)__half_as_ushort(ly) << 16);
}

__device__ __forceinline__ void mma16(float* d, const uint4& a, uint32_t b0, uint32_t b1) {
    asm("mma.sync.aligned.m16n8k16.row.col.f32.f16.f16.f32 "
        "{%0,%1,%2,%3}, {%4,%5,%6,%7}, {%8,%9}, {%0,%1,%2,%3};"
        : "+f"(d[0]), "+f"(d[1]), "+f"(d[2]), "+f"(d[3])
        : "r"(a.x), "r"(a.y), "r"(a.z), "r"(a.w), "r"(b0), "r"(b1));
}

__device__ __forceinline__ void cp_async16(uint32_t dst, const void* src) {
    asm volatile("cp.async.cg.shared.global [%0], [%1], 16;" :: "r"(dst), "l"(src));
}

// ---- pack: fp32 row-major [rows, 512] -> fp16 limb fragment layout ----
__global__ void __launch_bounds__(256)
pack_a16(const float* __restrict__ src, uint4* __restrict__ d0, uint4* __restrict__ d1)
{
    const uint32_t gid = blockIdx.x * 256 + threadIdx.x;   // 4,194,304 total
    const int lane = gid & 31;
    const int mt   = (gid >> 5) & 7;
    const int k16  = (gid >> 8) & 1;
    const int kc   = (gid >> 9) & 15;
    const int mblk = gid >> 13;
    const int g = lane >> 2, tig = lane & 3;
    const int row0 = mblk * 128 + mt * 16 + g;
    const int k0 = kc * 32 + k16 * 16 + tig * 2;
    const float2 p00 = *(const float2*)(src + (size_t)row0 * KDIM + k0);
    const float2 p10 = *(const float2*)(src + (size_t)(row0 + 8) * KDIM + k0);
    const float2 p01 = *(const float2*)(src + (size_t)row0 * KDIM + k0 + 8);
    const float2 p11 = *(const float2*)(src + (size_t)(row0 + 8) * KDIM + k0 + 8);
    uint4 h, l;
    split2(p00.x, p00.y, h.x, l.x);
    split2(p10.x, p10.y, h.y, l.y);
    split2(p01.x, p01.y, h.z, l.z);
    split2(p11.x, p11.y, h.w, l.w);
    d0[gid] = h;
    d1[gid] = l;
}

__global__ void __launch_bounds__(256)
pack_w16(const float* __restrict__ src, uint4* __restrict__ d0, uint4* __restrict__ d1)
{
    const uint32_t gid = blockIdx.x * 256 + threadIdx.x;
    const int lane = gid & 31;
    const int np   = (gid >> 5) & 7;
    const int k16  = (gid >> 8) & 1;
    const int kc   = (gid >> 9) & 15;
    const int nblk = gid >> 13;
    const int g = lane >> 2, tig = lane & 3;
    const int n0 = nblk * 128 + np * 16 + g;
    const int k0 = kc * 32 + k16 * 16 + tig * 2;
    const float2 q00 = *(const float2*)(src + (size_t)n0 * KDIM + k0);
    const float2 q01 = *(const float2*)(src + (size_t)n0 * KDIM + k0 + 8);
    const float2 q10 = *(const float2*)(src + (size_t)(n0 + 8) * KDIM + k0);
    const float2 q11 = *(const float2*)(src + (size_t)(n0 + 8) * KDIM + k0 + 8);
    uint4 h, l;
    split2(q00.x, q00.y, h.x, l.x);
    split2(q01.x, q01.y, h.y, l.y);
    split2(q10.x, q10.y, h.z, l.z);
    split2(q11.x, q11.y, h.w, l.w);
    d0[gid] = h;
    d1[gid] = l;
}

// ---- fused fp16x2-limb GEMM layer: act_clip(A @ W^T + bias) ----
// CTA 128x128 tile, BK=32, 3-stage cp.async pipeline (1 sync/chunk), 8 warps.
__global__ void __launch_bounds__(256, 2)
fused_layer16(const uint4* __restrict__ A0, const uint4* __restrict__ A1,
              const uint4* __restrict__ B0, const uint4* __restrict__ B1,
              const float* __restrict__ bias,
              const int*   __restrict__ fid,
              const float* __restrict__ mx,
              uint32_t* __restrict__ C0, uint32_t* __restrict__ C1,
              float* __restrict__ Cout,
              int Nout, int split_out)
{
    extern __shared__ __align__(16) uint32_t smw[];

    const int tid = threadIdx.x;
    const int w   = tid >> 5;
    const int l   = tid & 31;
    const int bn  = blockIdx.x * 128;
    const int wm  = w & 3;            // m block (rows wm*32)
    const int wn  = w >> 2;           // n half (cols wn*64)

    const uint32_t smem_addr = (uint32_t)__cvta_generic_to_shared(smw);
    const size_t a_base = (size_t)blockIdx.y * A_BLK_U4;
    const size_t b_base = (size_t)blockIdx.x * W_NBLK_U4;

    float acc[2][8][4];
    #pragma unroll
    for (int i = 0; i < 2; ++i)
        #pragma unroll
        for (int u = 0; u < 8; ++u)
            #pragma unroll
            for (int r = 0; r < 4; ++r) acc[i][u][r] = 0.0f;

    #define ISSUE_CHUNK(kc_) do {                                             \
        const uint32_t dstb = smem_addr + ((kc_) % NSTAGE) * (STAGE_WORDS*4); \
        const uint4* pA0 = A0 + a_base + (size_t)(kc_) * 512;                 \
        const uint4* pA1 = A1 + a_base + (size_t)(kc_) * 512;                 \
        const uint4* pB0 = B0 + b_base + (size_t)(kc_) * 512;                 \
        const uint4* pB1 = B1 + b_base + (size_t)(kc_) * 512;                 \
        _Pragma("unroll")                                                     \
        for (int j = 0; j < 2; ++j) {                                         \
            const int g16 = tid + j * 256;                                    \
            cp_async16(dstb +         g16 * 16, pA0 + g16);                   \
            cp_async16(dstb +  8192 + g16 * 16, pA1 + g16);                   \
            cp_async16(dstb + 16384 + g16 * 16, pB0 + g16);                   \
            cp_async16(dstb + 24576 + g16 * 16, pB1 + g16);                   \
        }                                                                     \
        asm volatile("cp.async.commit_group;" ::: "memory");                  \
    } while (0)

    // Prologue: 2 chunks in flight.
    ISSUE_CHUNK(0);
    ISSUE_CHUNK(1);

    constexpr int NCHUNK = KDIM / 32;   // 16
    for (int kc = 0; kc < NCHUNK; ++kc) {
        // chunk kc complete (<=1 newer group may still be pending)
        asm volatile("cp.async.wait_group 1;" ::: "memory");
        __syncthreads();

        // Refill the slot consumed at kc-1 (all reads ordered by the sync above).
        if (kc + 2 < NCHUNK) ISSUE_CHUNK(kc + 2);

        const uint32_t* sw = smw + (kc % NSTAGE) * STAGE_WORDS;
        #pragma unroll
        for (int k16 = 0; k16 < 2; ++k16) {
            const uint32_t* awb = sw + k16 * 1024;
            const uint4 ah0 = *(const uint4*)(awb + (wm * 2 + 0) * 128 + l * 4);
            const uint4 ah1 = *(const uint4*)(awb + (wm * 2 + 1) * 128 + l * 4);
            const uint4 al0 = *(const uint4*)(awb + 2048 + (wm * 2 + 0) * 128 + l * 4);
            const uint4 al1 = *(const uint4*)(awb + 2048 + (wm * 2 + 1) * 128 + l * 4);
            const uint32_t* bwb = sw + 4096 + k16 * 1024;
            #pragma unroll
            for (int pp = 0; pp < 4; ++pp) {
                const int np = wn * 4 + pp;
                const uint4 bh = *(const uint4*)(bwb + np * 128 + l * 4);
                const uint4 bl = *(const uint4*)(bwb + 2048 + np * 128 + l * 4);
                // group u = pp*2 (regs .x,.y), group u+1 (regs .z,.w)
                // acc += h0a*h0b + h0a*h1b + h1a*h0b
                mma16(acc[0][pp * 2],     ah0, bh.x, bh.y);
                mma16(acc[0][pp * 2],     ah0, bl.x, bl.y);
                mma16(acc[0][pp * 2],     al0, bh.x, bh.y);
                mma16(acc[1][pp * 2],     ah1, bh.x, bh.y);
                mma16(acc[1][pp * 2],     ah1, bl.x, bl.y);
                mma16(acc[1][pp * 2],     al1, bh.x, bh.y);
                mma16(acc[0][pp * 2 + 1], ah0, bh.z, bh.w);
                mma16(acc[0][pp * 2 + 1], ah0, bl.z, bl.w);
                mma16(acc[0][pp * 2 + 1], al0, bh.z, bh.w);
                mma16(acc[1][pp * 2 + 1], ah1, bh.z, bh.w);
                mma16(acc[1][pp * 2 + 1], ah1, bl.z, bl.w);
                mma16(acc[1][pp * 2 + 1], al1, bh.z, bh.w);
            }
        }
    }

    // ---- epilogue ----
    const int g = l >> 2;
    #pragma unroll
    for (int u = 0; u < 8; ++u) {
        const int col = bn + wn * 64 + u * 8 + (l & 3) * 2;
        const float bv0 = __ldg(bias + col);
        const float bv1 = __ldg(bias + col + 1);
        const int   f0  = __ldg(fid + col);
        const int   f1  = __ldg(fid + col + 1);
        const float m0  = __ldg(mx + col);
        const float m1  = __ldg(mx + col + 1);
        #pragma unroll
        for (int i = 0; i < 2; ++i) {
            const float* a4 = acc[i][u];
            const float v00 = act_clip(a4[0] + bv0, f0, m0);  // (row g,   col)
            const float v01 = act_clip(a4[1] + bv1, f1, m1);  // (row g,   col+1)
            const float v10 = act_clip(a4[2] + bv0, f0, m0);  // (row g+8, col)
            const float v11 = act_clip(a4[3] + bv1, f1, m1);  // (row g+8, col+1)
            if (split_out) {
                // packed fp16-limb write for next layer's A (64-bit merged stores:
                // words wb+2kb and wb+1+2kb are adjacent and 8B-aligned)
                const int kc_  = col >> 5;
                const int k16_ = (col >> 4) & 1;
                const int kb   = (col >> 3) & 1;
                const int mt_  = wm * 2 + i;
                const size_t wb =
                    ((((size_t)blockIdx.y * 16 + kc_) * 2 + k16_) * 8 + mt_) * 128
                    + (size_t)l * 4;
                uint32_t w0h, w0l, w1h, w1l;
                split2(v00, v01, w0h, w0l);
                split2(v10, v11, w1h, w1l);
                *(uint2*)(C0 + wb + 2 * kb) = make_uint2(w0h, w1h);
                *(uint2*)(C1 + wb + 2 * kb) = make_uint2(w0l, w1l);
            } else {
                const int row0 = blockIdx.y * 128 + wm * 32 + i * 16 + g;
                *(float2*)(Cout + (size_t)row0 * Nout + col)       = make_float2(v00, v01);
                *(float2*)(Cout + (size_t)(row0 + 8) * Nout + col) = make_float2(v10, v11);
            }
        }
    }
}

extern "C" void kernel_launch(void* const* d_in, const int* in_sizes, int n_in,
                              void* d_out, int out_size) {
    const float* x      = (const float*)d_in[0];   // [65536, 512]
    const float* W_in   = (const float*)d_in[1];
    const float* b_in   = (const float*)d_in[2];
    const float* W_h    = (const float*)d_in[3];
    const float* b_h    = (const float*)d_in[4];
    const float* W_out  = (const float*)d_in[5];
    const float* b_out  = (const float*)d_in[6];
    const float* m_in   = (const float*)d_in[7];
    const float* m_h    = (const float*)d_in[8];
    const float* m_out  = (const float*)d_in[9];
    const int*   fid_in = (const int*)d_in[10];
    const int*   fid_h  = (const int*)d_in[11];
    const int*   fid_out= (const int*)d_in[12];
    float* out = (float*)d_out;                    // [65536, 128]

    uint4 *A0a, *A1a, *A0b, *A1b, *W0, *W1;
    cudaGetSymbolAddress((void**)&A0a, g_A0a);
    cudaGetSymbolAddress((void**)&A1a, g_A1a);
    cudaGetSymbolAddress((void**)&A0b, g_A0b);
    cudaGetSymbolAddress((void**)&A1b, g_A1b);
    cudaGetSymbolAddress((void**)&W0, g_W0);
    cudaGetSymbolAddress((void**)&W1, g_W1);

    cudaFuncSetAttribute(fused_layer16,
                         cudaFuncAttributeMaxDynamicSharedMemorySize, SMEM_BYTES);

    // ---- one-time packing into fp16 limb fragment layout ----
    pack_a16<<<16384, 256>>>(x, A0a, A1a);
    pack_w16<<<128, 256>>>(W_in,  W0,                W1);                   // 4 n_blks
    pack_w16<<<512, 256>>>(W_h,   W0 + 4 * W_NBLK_U4,  W1 + 4 * W_NBLK_U4); // 16 n_blks
    pack_w16<<<32, 256>>>(W_out,  W0 + 20 * W_NBLK_U4, W1 + 20 * W_NBLK_U4);// 1 n_blk

    dim3 blk(256);
    dim3 g512(4, B_TOTAL / 128);
    dim3 g128(1, B_TOTAL / 128);

    // input layer: packed A(a) -> packed A(b)
    fused_layer16<<<g512, blk, SMEM_BYTES>>>(A0a, A1a, W0, W1,
                                             b_in, fid_in, m_in,
                                             (uint32_t*)A0b, (uint32_t*)A1b,
                                             nullptr, 512, 1);

    // 4 hidden layers, ping-pong
    const uint4* c0 = A0b; const uint4* c1 = A1b;
    uint4* n0 = A0a;       uint4* n1 = A1a;
    for (int i = 0; i < 4; ++i) {
        const size_t woff = (size_t)(4 + 4 * i) * W_NBLK_U4;
        fused_layer16<<<g512, blk, SMEM_BYTES>>>(c0, c1, W0 + woff, W1 + woff,
                                                 b_h + i * 512,
                                                 fid_h + i * 512,
                                                 m_h + i * 512,
                                                 (uint32_t*)n0, (uint32_t*)n1,
                                                 nullptr, 512, 1);
        uint4* t0 = n0; uint4* t1 = n1;
        n0 = (uint4*)c0; n1 = (uint4*)c1;
        c0 = t0; c1 = t1;
    }

    // output layer: plain fp32 row-major out
    fused_layer16<<<g128, blk, SMEM_BYTES>>>(c0, c1,
                                             W0 + 20 * W_NBLK_U4, W1 + 20 * W_NBLK_U4,
                                             b_out, fid_out, m_out,
                                             nullptr, nullptr, out, 128, 0);
}